// round 3
// baseline (speedup 1.0000x reference)
#include <cuda_runtime.h>
#include <math.h>

#define Bn 64
#define Sn 2048
#define Hn 512
#define An 512

// Scratch (no allocations allowed in kernel_launch)
__device__ float g_dec_proj[Bn * An];
__device__ float g_score[Bn * Sn];

// ---------------------------------------------------------------------------
// Kernel 1: dec_proj[b,a] = dec_hidden[b,:] . W_dec[a,:]
// ---------------------------------------------------------------------------
__global__ void dec_proj_k(const float* __restrict__ dec_hidden,
                           const float* __restrict__ W_dec) {
    __shared__ float dh[Hn];
    int b = blockIdx.x;
    for (int i = threadIdx.x; i < Hn; i += blockDim.x) dh[i] = dec_hidden[b * Hn + i];
    __syncthreads();
    for (int a = threadIdx.x; a < An; a += blockDim.x) {
        const float* w = W_dec + (size_t)a * Hn;
        float s = 0.f;
#pragma unroll 8
        for (int k = 0; k < Hn; k++) s = fmaf(dh[k], w[k], s);
        g_dec_proj[b * An + a] = s;
    }
}

// ---------------------------------------------------------------------------
// Kernel 2 (hot): score[b,s] = sum_a v[a] * tanh(enc[b,s,:].W_enc[a,:] + dec_proj[b,a])
// fp32 GEMM with packed f32x2 FMA (Blackwell FFMA2): 64(m) x 128(a) block tile,
// K-chunk 32, 4x8 per-thread micro-tile with a-pairs packed into f32x2 accs.
// W tile stored transposed + pair-packed (float2 [a/2][k]) for direct LDS.64.
// Register-prefetch pipeline hides LDG latency. Fused tanh/v/reduce epilogue.
// ---------------------------------------------------------------------------
__global__ __launch_bounds__(256, 2) void score_k(const float* __restrict__ enc,
                                                  const float* __restrict__ W_enc,
                                                  const float* __restrict__ v) {
    __shared__ float  es[64][33];    // enc tile [row][k], +1 pad
    __shared__ float2 ws2[64][33];   // W tile  [a/2][k], a-pairs packed, +1 pad
    __shared__ float  red[64][17];   // cross-thread score reduction

    int tid = threadIdx.x;
    int tc = tid & 15;        // a-group: 8 a's = 4 f32x2 pairs
    int tr = tid >> 4;        // m-group: 4 rows
    int mbase = blockIdx.x * 64;
    int b = mbase >> 11;              // mbase / Sn  (Sn = 2048)
    int sbase = mbase & (Sn - 1);

    float part[4];
#pragma unroll
    for (int i = 0; i < 4; i++) part[i] = 0.f;

    const int NCHUNK = (An / 128) * (Hn / 32);   // 64 flat chunks
    float4 pe[2], pw[4];

    // prefetch flat chunk 0 (at=0, kc=0)
#pragma unroll
    for (int l = 0; l < 2; l++) {
        int idx = tid + l * 256;            // es: 512 float4 slots
        int row = idx >> 3, c4 = (idx & 7) << 2;
        pe[l] = *(const float4*)(enc + (size_t)(mbase + row) * Hn + c4);
    }
#pragma unroll
    for (int l = 0; l < 4; l++) {
        int idx = tid + l * 256;            // ws: 1024 float4 slots
        int row = idx >> 3, c4 = (idx & 7) << 2;
        pw[l] = *(const float4*)(W_enc + (size_t)row * Hn + c4);
    }
    int flat = 0;

    for (int at = 0; at < An / 128; at++) {
        unsigned long long acc[4][4];       // [i][jp] packed pair accumulators
#pragma unroll
        for (int i = 0; i < 4; i++)
#pragma unroll
            for (int jp = 0; jp < 4; jp++) acc[i][jp] = 0ull;

        for (int kc = 0; kc < Hn; kc += 32) {
            // commit prefetched tiles to smem
#pragma unroll
            for (int l = 0; l < 2; l++) {
                int idx = tid + l * 256;
                int row = idx >> 3, c4 = (idx & 7) << 2;
                es[row][c4 + 0] = pe[l].x; es[row][c4 + 1] = pe[l].y;
                es[row][c4 + 2] = pe[l].z; es[row][c4 + 3] = pe[l].w;
            }
#pragma unroll
            for (int l = 0; l < 4; l++) {
                int idx = tid + l * 256;
                int row = idx >> 3, c4 = (idx & 7) << 2;
                float* wf = (float*)&ws2[row >> 1][0] + (row & 1);
                wf[(c4 + 0) * 2] = pw[l].x; wf[(c4 + 1) * 2] = pw[l].y;
                wf[(c4 + 2) * 2] = pw[l].z; wf[(c4 + 3) * 2] = pw[l].w;
            }
            __syncthreads();

            // prefetch next flat chunk (crosses a-tile boundaries)
            flat++;
            if (flat < NCHUNK) {
                int at2 = flat >> 4;
                int kc2 = (flat & 15) << 5;
#pragma unroll
                for (int l = 0; l < 2; l++) {
                    int idx = tid + l * 256;
                    int row = idx >> 3, c4 = (idx & 7) << 2;
                    pe[l] = *(const float4*)(enc + (size_t)(mbase + row) * Hn + kc2 + c4);
                }
#pragma unroll
                for (int l = 0; l < 4; l++) {
                    int idx = tid + l * 256;
                    int row = idx >> 3, c4 = (idx & 7) << 2;
                    pw[l] = *(const float4*)(W_enc + (size_t)(at2 * 128 + row) * Hn + kc2 + c4);
                }
            }

            // compute on current smem tile: packed f32x2 FMAs
#pragma unroll 4
            for (int k = 0; k < 32; k++) {
                unsigned long long ee[4];
#pragma unroll
                for (int i = 0; i < 4; i++) {
                    float e = es[tr * 4 + i][k];
                    asm("mov.b64 %0, {%1,%1};" : "=l"(ee[i]) : "f"(e));
                }
#pragma unroll
                for (int jp = 0; jp < 4; jp++) {
                    unsigned long long wp =
                        *(const unsigned long long*)&ws2[tc * 4 + jp][k];
#pragma unroll
                    for (int i = 0; i < 4; i++) {
                        asm("fma.rn.f32x2 %0, %1, %2, %0;"
                            : "+l"(acc[i][jp]) : "l"(ee[i]), "l"(wp));
                    }
                }
            }
            __syncthreads();
        }
        // fused epilogue: + dec_proj, tanh, * v, partial sum over this a-tile
        int a0 = at * 128 + tc * 8;
#pragma unroll
        for (int jp = 0; jp < 4; jp++) {
            int a = a0 + jp * 2;
            float v0 = v[a], v1 = v[a + 1];
            float d0 = g_dec_proj[b * An + a];
            float d1 = g_dec_proj[b * An + a + 1];
#pragma unroll
            for (int i = 0; i < 4; i++) {
                float lo, hi;
                asm("mov.b64 {%0,%1}, %2;" : "=f"(lo), "=f"(hi) : "l"(acc[i][jp]));
                part[i] += v0 * tanhf(lo + d0);
                part[i] += v1 * tanhf(hi + d1);
            }
        }
    }

    // reduce partial scores across the 16 a-groups
#pragma unroll
    for (int i = 0; i < 4; i++) red[tr * 4 + i][tc] = part[i];
    __syncthreads();
    if (tid < 64) {
        float s = 0.f;
#pragma unroll
        for (int c = 0; c < 16; c++) s += red[tid][c];
        g_score[b * Sn + sbase + tid] = s;
    }
}

// ---------------------------------------------------------------------------
// Kernel 3: softmax over s per batch, writes attn_weights to output
// ---------------------------------------------------------------------------
__global__ void softmax_k(float* __restrict__ attn_out) {
    __shared__ float red[256];
    int b = blockIdx.x;
    int t = threadIdx.x;
    float m = -1e30f;
    for (int s = t; s < Sn; s += 256) m = fmaxf(m, g_score[b * Sn + s]);
    red[t] = m; __syncthreads();
    for (int o = 128; o > 0; o >>= 1) {
        if (t < o) red[t] = fmaxf(red[t], red[t + o]);
        __syncthreads();
    }
    m = red[0]; __syncthreads();
    float sum = 0.f;
    for (int s = t; s < Sn; s += 256) {
        float e = expf(g_score[b * Sn + s] - m);
        g_score[b * Sn + s] = e;
        sum += e;
    }
    red[t] = sum; __syncthreads();
    for (int o = 128; o > 0; o >>= 1) {
        if (t < o) red[t] += red[t + o];
        __syncthreads();
    }
    float inv = 1.f / red[0];
    for (int s = t; s < Sn; s += 256) attn_out[b * Sn + s] = g_score[b * Sn + s] * inv;
}

// ---------------------------------------------------------------------------
// Kernel 4: context[b,e] = sum_s attn[b,s] * enc[b,s,e]   (s split across 8 blocks)
// ---------------------------------------------------------------------------
__global__ void zero_ctx_k(float* __restrict__ ctx) {
    int i = blockIdx.x * blockDim.x + threadIdx.x;
    if (i < Bn * Hn) ctx[i] = 0.f;
}

__global__ __launch_bounds__(512) void context_k(const float* __restrict__ enc,
                                                 const float* __restrict__ attn,
                                                 float* __restrict__ ctx) {
    int b = blockIdx.x;
    int sc = blockIdx.y;      // 8 chunks of 256 s
    int e = threadIdx.x;      // 512 e's
    int s0 = sc * 256;
    const float* ep = enc + ((size_t)b * Sn + s0) * Hn + e;
    const float* wp = attn + b * Sn + s0;
    float acc = 0.f;
#pragma unroll 4
    for (int s = 0; s < 256; s++) acc = fmaf(wp[s], ep[(size_t)s * Hn], acc);
    atomicAdd(&ctx[b * Hn + e], acc);
}

// ---------------------------------------------------------------------------
extern "C" void kernel_launch(void* const* d_in, const int* in_sizes, int n_in,
                              void* d_out, int out_size) {
    const float* enc   = (const float*)d_in[0];  // [B,S,ENC_H]
    const float* dec   = (const float*)d_in[1];  // [B,DEC_H]
    const float* W_enc = (const float*)d_in[2];  // [ATTN,ENC_H]
    const float* W_dec = (const float*)d_in[3];  // [ATTN,DEC_H]
    const float* v     = (const float*)d_in[4];  // [1,ATTN]

    float* ctx  = (float*)d_out;            // context  [B,ENC_H]
    float* attn = (float*)d_out + Bn * Hn;  // attn_weights [B,S]

    zero_ctx_k<<<(Bn * Hn + 255) / 256, 256>>>(ctx);
    dec_proj_k<<<Bn, 256>>>(dec, W_dec);
    score_k<<<(Bn * Sn) / 64, 256>>>(enc, W_enc, v);
    softmax_k<<<Bn, 256>>>(attn);
    context_k<<<dim3(Bn, 8), 512>>>(enc, attn, ctx);
}

// round 7
// speedup vs baseline: 3.5537x; 3.5537x over previous
#include <cuda_runtime.h>
#include <cuda_bf16.h>
#include <math.h>
#include <stdint.h>

#define Bn 64
#define Sn 2048
#define Hn 512
#define An 512

// Scratch (no device allocations allowed)
__device__ float g_dec_proj[Bn * An];
__device__ float g_score[Bn * Sn];
__device__ __nv_bfloat16 g_Whi[An * Hn];
__device__ __nv_bfloat16 g_Wlo[An * Hn];

// Warp-level bf16 MMA (baseline PTX, valid on target sm_103)
__device__ __forceinline__ void mma_bf16(float* d, uint32_t a0, uint32_t a1,
                                         uint32_t a2, uint32_t a3,
                                         uint32_t b0, uint32_t b1) {
    asm volatile(
        "mma.sync.aligned.m16n8k16.row.col.f32.bf16.bf16.f32 "
        "{%0,%1,%2,%3}, {%4,%5,%6,%7}, {%8,%9}, {%0,%1,%2,%3};"
        : "+f"(d[0]), "+f"(d[1]), "+f"(d[2]), "+f"(d[3])
        : "r"(a0), "r"(a1), "r"(a2), "r"(a3), "r"(b0), "r"(b1));
}

// ---------------------------------------------------------------------------
// W_enc fp32 -> bf16 hi/lo split (once per launch, ~1MB)
// ---------------------------------------------------------------------------
__global__ void wsplit_k(const float* __restrict__ W_enc) {
    int i = blockIdx.x * blockDim.x + threadIdx.x;
    if (i < An * Hn) {
        float x = W_enc[i];
        __nv_bfloat16 h = __float2bfloat16_rn(x);
        g_Whi[i] = h;
        g_Wlo[i] = __float2bfloat16_rn(x - __bfloat162float(h));
    }
}

// ---------------------------------------------------------------------------
// dec_proj[b,a] = dec_hidden[b,:] . W_dec[a,:]
// ---------------------------------------------------------------------------
__global__ void dec_proj_k(const float* __restrict__ dec_hidden,
                           const float* __restrict__ W_dec) {
    __shared__ float dh[Hn];
    int b = blockIdx.x;
    for (int i = threadIdx.x; i < Hn; i += blockDim.x) dh[i] = dec_hidden[b * Hn + i];
    __syncthreads();
    for (int a = threadIdx.x; a < An; a += blockDim.x) {
        const float* w = W_dec + (size_t)a * Hn;
        float s = 0.f;
#pragma unroll 8
        for (int k = 0; k < Hn; k++) s = fmaf(dh[k], w[k], s);
        g_dec_proj[b * An + a] = s;
    }
}

// ---------------------------------------------------------------------------
// HOT: score via warp-level bf16 mma.sync, 3-term hi/lo split.
// CTA: 128 m-rows x (4 a-tiles of 128). 8 warps as 4m x 2n.
// Per warp per a-tile: 32 rows x 64 cols -> acc[2][8][4].
// Smem chunks: 128 x 32 (stride 40 bf16 = 80B, bank-conflict-free frag loads).
// Fused epilogue: +dec_proj, tanh, *v, per-row reduce. Score only to gmem.
// ---------------------------------------------------------------------------
__global__ __launch_bounds__(256, 2) void score_mma_k(const float* __restrict__ enc,
                                                      const float* __restrict__ v) {
    __shared__ __nv_bfloat16 sAhi[128 * 40], sAlo[128 * 40];
    __shared__ __nv_bfloat16 sBhi[128 * 40], sBlo[128 * 40];
    __shared__ float dp_s[An], vs_s[An];
    __shared__ float red[128][2];

    int tid = threadIdx.x;
    int lane = tid & 31, wid = tid >> 5;
    int wm = wid >> 1, wn = wid & 1;   // 4m x 2n warp grid
    int g = lane >> 2, t = lane & 3;   // mma group / quad ids
    int mbase = blockIdx.x * 128;
    int b = mbase >> 11;               // / Sn
    int srow = mbase & (Sn - 1);

    for (int i = tid; i < An; i += 256) {
        dp_s[i] = g_dec_proj[b * An + i];
        vs_s[i] = v[i];
    }

    float part[4] = {0.f, 0.f, 0.f, 0.f};

    for (int at = 0; at < 4; at++) {
        float acc[2][8][4];
#pragma unroll
        for (int mt = 0; mt < 2; mt++)
#pragma unroll
            for (int nt = 0; nt < 8; nt++)
#pragma unroll
                for (int j = 0; j < 4; j++) acc[mt][nt][j] = 0.f;

        for (int kc = 0; kc < 16; kc++) {
            __syncthreads();   // protect prior iteration's fragment reads
            // --- A: 128x32 fp32 -> bf16 hi/lo, 16B stores, coalesced LDG ---
#pragma unroll
            for (int h = 0; h < 2; h++) {
                int s = tid + h * 256;             // 512 segs of 8 elems
                int row = s >> 2, ko = (s & 3) * 8;
                const float* src = enc + (size_t)(mbase + row) * Hn + kc * 32 + ko;
                float4 x0 = *(const float4*)src;
                float4 x1 = *(const float4*)(src + 4);
                float xs[8] = {x0.x, x0.y, x0.z, x0.w, x1.x, x1.y, x1.z, x1.w};
                __nv_bfloat16 hi[8], lo[8];
#pragma unroll
                for (int e = 0; e < 8; e++) {
                    hi[e] = __float2bfloat16_rn(xs[e]);
                    lo[e] = __float2bfloat16_rn(xs[e] - __bfloat162float(hi[e]));
                }
                *(uint4*)(&sAhi[row * 40 + ko]) = *(uint4*)hi;
                *(uint4*)(&sAlo[row * 40 + ko]) = *(uint4*)lo;
            }
            // --- B: copy pre-split W chunk (128a x 32k, hi+lo) ---
#pragma unroll
            for (int h = 0; h < 2; h++) {
                int s = tid + h * 256;
                int row = s >> 2, ko = (s & 3) * 8;
                size_t goff = (size_t)(at * 128 + row) * Hn + kc * 32 + ko;
                *(uint4*)(&sBhi[row * 40 + ko]) = *(const uint4*)(g_Whi + goff);
                *(uint4*)(&sBlo[row * 40 + ko]) = *(const uint4*)(g_Wlo + goff);
            }
            __syncthreads();

#pragma unroll
            for (int ks = 0; ks < 2; ks++) {
                int kb = ks * 16 + t * 2;
                uint32_t ah[2][4], al[2][4];
#pragma unroll
                for (int mt = 0; mt < 2; mt++) {
                    int r0 = wm * 32 + mt * 16 + g;
                    ah[mt][0] = *(uint32_t*)(&sAhi[r0 * 40 + kb]);
                    ah[mt][1] = *(uint32_t*)(&sAhi[(r0 + 8) * 40 + kb]);
                    ah[mt][2] = *(uint32_t*)(&sAhi[r0 * 40 + kb + 8]);
                    ah[mt][3] = *(uint32_t*)(&sAhi[(r0 + 8) * 40 + kb + 8]);
                    al[mt][0] = *(uint32_t*)(&sAlo[r0 * 40 + kb]);
                    al[mt][1] = *(uint32_t*)(&sAlo[(r0 + 8) * 40 + kb]);
                    al[mt][2] = *(uint32_t*)(&sAlo[r0 * 40 + kb + 8]);
                    al[mt][3] = *(uint32_t*)(&sAlo[(r0 + 8) * 40 + kb + 8]);
                }
#pragma unroll
                for (int nt = 0; nt < 8; nt++) {
                    int c0 = wn * 64 + nt * 8 + g;
                    uint32_t bh0 = *(uint32_t*)(&sBhi[c0 * 40 + kb]);
                    uint32_t bh1 = *(uint32_t*)(&sBhi[c0 * 40 + kb + 8]);
                    uint32_t bl0 = *(uint32_t*)(&sBlo[c0 * 40 + kb]);
                    uint32_t bl1 = *(uint32_t*)(&sBlo[c0 * 40 + kb + 8]);
#pragma unroll
                    for (int mt = 0; mt < 2; mt++) {
                        mma_bf16(acc[mt][nt], ah[mt][0], ah[mt][1], ah[mt][2], ah[mt][3], bh0, bh1);
                        mma_bf16(acc[mt][nt], ah[mt][0], ah[mt][1], ah[mt][2], ah[mt][3], bl0, bl1);
                        mma_bf16(acc[mt][nt], al[mt][0], al[mt][1], al[mt][2], al[mt][3], bh0, bh1);
                    }
                }
            }
        }
        // fused epilogue for this a-tile: +dec_proj, tanh, *v, row partials
#pragma unroll
        for (int mt = 0; mt < 2; mt++)
#pragma unroll
            for (int nt = 0; nt < 8; nt++)
#pragma unroll
                for (int j = 0; j < 4; j++) {
                    int a = at * 128 + wn * 64 + nt * 8 + 2 * t + (j & 1);
                    part[mt * 2 + (j >> 1)] += vs_s[a] * tanhf(acc[mt][nt][j] + dp_s[a]);
                }
    }

    // reduce over quad (cols within fragment row)
#pragma unroll
    for (int p = 0; p < 4; p++) {
        part[p] += __shfl_xor_sync(0xffffffffu, part[p], 1);
        part[p] += __shfl_xor_sync(0xffffffffu, part[p], 2);
    }
    if (t == 0) {
#pragma unroll
        for (int mt = 0; mt < 2; mt++)
#pragma unroll
            for (int rh = 0; rh < 2; rh++)
                red[wm * 32 + mt * 16 + g + rh * 8][wn] = part[mt * 2 + rh];
    }
    __syncthreads();
    if (tid < 128) g_score[b * Sn + srow + tid] = red[tid][0] + red[tid][1];
}

// ---------------------------------------------------------------------------
// softmax over s per batch, writes attn_weights
// ---------------------------------------------------------------------------
__global__ void softmax_k(float* __restrict__ attn_out) {
    __shared__ float red[256];
    int b = blockIdx.x;
    int t = threadIdx.x;
    float m = -1e30f;
    for (int s = t; s < Sn; s += 256) m = fmaxf(m, g_score[b * Sn + s]);
    red[t] = m; __syncthreads();
    for (int o = 128; o > 0; o >>= 1) {
        if (t < o) red[t] = fmaxf(red[t], red[t + o]);
        __syncthreads();
    }
    m = red[0]; __syncthreads();
    float sum = 0.f;
    for (int s = t; s < Sn; s += 256) {
        float e = expf(g_score[b * Sn + s] - m);
        g_score[b * Sn + s] = e;
        sum += e;
    }
    red[t] = sum; __syncthreads();
    for (int o = 128; o > 0; o >>= 1) {
        if (t < o) red[t] += red[t + o];
        __syncthreads();
    }
    float inv = 1.f / red[0];
    for (int s = t; s < Sn; s += 256) attn_out[b * Sn + s] = g_score[b * Sn + s] * inv;
}

// ---------------------------------------------------------------------------
// context[b,e] = sum_s attn[b,s] * enc[b,s,e]
// ---------------------------------------------------------------------------
__global__ void zero_ctx_k(float* __restrict__ ctx) {
    int i = blockIdx.x * blockDim.x + threadIdx.x;
    if (i < Bn * Hn) ctx[i] = 0.f;
}
__global__ __launch_bounds__(512) void context_k(const float* __restrict__ enc,
                                                 const float* __restrict__ attn,
                                                 float* __restrict__ ctx) {
    int b = blockIdx.x;
    int sc = blockIdx.y;
    int e = threadIdx.x;
    int s0 = sc * 256;
    const float* ep = enc + ((size_t)b * Sn + s0) * Hn + e;
    const float* wp = attn + b * Sn + s0;
    float acc = 0.f;
#pragma unroll 4
    for (int s = 0; s < 256; s++) acc = fmaf(wp[s], ep[(size_t)s * Hn], acc);
    atomicAdd(&ctx[b * Hn + e], acc);
}

// ---------------------------------------------------------------------------
extern "C" void kernel_launch(void* const* d_in, const int* in_sizes, int n_in,
                              void* d_out, int out_size) {
    const float* enc   = (const float*)d_in[0];
    const float* dec   = (const float*)d_in[1];
    const float* W_enc = (const float*)d_in[2];
    const float* W_dec = (const float*)d_in[3];
    const float* v     = (const float*)d_in[4];

    float* ctx  = (float*)d_out;
    float* attn = (float*)d_out + Bn * Hn;

    zero_ctx_k<<<(Bn * Hn + 255) / 256, 256>>>(ctx);
    wsplit_k<<<(An * Hn + 255) / 256, 256>>>(W_enc);
    dec_proj_k<<<Bn, 256>>>(dec, W_dec);
    score_mma_k<<<(Bn * Sn) / 128, 256>>>(enc, v);
    softmax_k<<<Bn, 256>>>(attn);
    context_k<<<dim3(Bn, 8), 512>>>(enc, attn, ctx);
}